// round 14
// baseline (speedup 1.0000x reference)
#include <cuda_runtime.h>
#include <cuda_fp16.h>
#include <cstdint>

#define NIMG 64
#define DIM  256
#define HW   1024
#define MTOT 65536
#define KCODES 1024
#define ZQ_ELEMS 16777216

#define GAP_THRESH 6e-4f

__device__ float  g_enorm[KCODES];
__device__ int    g_idx[MTOT];
__device__ int    g_cand[MTOT * 4];
__device__ int    g_work[MTOT];
__device__ int    g_nwork;
__device__ double g_loss;
__device__ __half g_ehi[KCODES * DIM];   // fp16(1024*emb)

// ---------------- smem layout (bytes), M-tile = 64, 2 BIG E buffers ----------------
// chunk = 128 codes x 128 halves (256B data, 272B padded row)
#define ZH_OFF 0                  // 64 rows x 264 halves (528B stride) = 33792
#define EB_OFF 33792              // 2 x (128 codes x 272B) = 69632 -> ends 103424
#define EB_SZ  34816
#define EN_OFF 103424             // 1024 f32 (enorm + 0.5) -> 107520
#define SMEM_ARG 107520
// aliased after main loop (E buffers dead): 64 rows x 4 wn x 4 u32 = 4096
#define CAND_OFF EB_OFF

__device__ __forceinline__ uint32_t smem_u32(const void* p) {
    uint32_t a;
    asm("{ .reg .u64 t; cvta.to.shared.u64 t, %1; cvt.u32.u64 %0, t; }" : "=r"(a) : "l"(p));
    return a;
}
#define LDSM4(r0,r1,r2,r3,addr) \
    asm volatile("ldmatrix.sync.aligned.m8n8.x4.shared.b16 {%0,%1,%2,%3}, [%4];" \
                 : "=r"(r0), "=r"(r1), "=r"(r2), "=r"(r3) : "r"(addr))
#define MMA_F16(c, a0,a1,a2,a3, b0,b1) \
    asm volatile("mma.sync.aligned.m16n8k16.row.col.f32.f16.f16.f32 " \
                 "{%0,%1,%2,%3}, {%4,%5,%6,%7}, {%8,%9}, {%0,%1,%2,%3};" \
                 : "+f"((c)[0]), "+f"((c)[1]), "+f"((c)[2]), "+f"((c)[3]) \
                 : "r"(a0), "r"(a1), "r"(a2), "r"(a3), "r"(b0), "r"(b1))

// insert p into ascending 4-list (branchless IMNMX chain) — merges only
__device__ __forceinline__ void ins4b(uint32_t* t, uint32_t p) {
    uint32_t c;
    c = umax(t[0], p); t[0] = umin(t[0], p);
    p = c;
    c = umax(t[1], p); t[1] = umin(t[1], p);
    p = c;
    c = umax(t[2], p); t[2] = umin(t[2], p);
    t[3] = umin(t[3], c);
}

// ==================== small kernels ====================
// identical to round-1 (bit-matching enorm values, used by exact rescore)
__global__ void k_enorm(const float* __restrict__ emb) {
    int k = blockIdx.x, lid = threadIdx.x;
    if (k == 0 && lid == 0) { g_loss = 0.0; g_nwork = 0; }
    const float* p = emb + (size_t)k * DIM + lid * 8;
    float4 a = *(const float4*)p;
    float4 b = *(const float4*)(p + 4);
    float s = a.x*a.x; s = fmaf(a.y,a.y,s); s = fmaf(a.z,a.z,s); s = fmaf(a.w,a.w,s);
    s = fmaf(b.x,b.x,s); s = fmaf(b.y,b.y,s); s = fmaf(b.z,b.z,s); s = fmaf(b.w,b.w,s);
    #pragma unroll
    for (int off = 16; off; off >>= 1) s += __shfl_xor_sync(0xffffffffu, s, off);
    if (lid == 0) g_enorm[k] = s;
}

__global__ void k_esplit(const float* __restrict__ emb) {
    int t = blockIdx.x * 256 + threadIdx.x;
    #pragma unroll
    for (int i = 0; i < 4; i++) {
        int id = t * 4 + i;
        g_ehi[id] = __float2half_rn(emb[id] * 1024.0f);
    }
}

// ==================== phase A: candidate search + gap-gated commit ====================
__global__ void __launch_bounds__(256, 2)
k_argmin_mma(const float* __restrict__ z) {
    extern __shared__ char smem[];
    const uint32_t sb = smem_u32(smem);
    const int tid = threadIdx.x;
    const int lane = tid & 31;
    const int warp = tid >> 5;
    const int wm = warp & 1;        // rows wm*32..+31
    const int wn = warp >> 1;       // cols wn*32..+31 within 128-code tile

    const int m0 = blockIdx.x * 64;
    const int n_img = m0 >> 10;
    const int hw0 = m0 & (HW - 1);

    // ---- per-thread loader offsets: 8 x 16B per thread per BIG chunk ----
    uint32_t dsto[8]; uint64_t srco[8];
    {
        const uint64_t ebase = (uint64_t)__cvta_generic_to_global(g_ehi);
        #pragma unroll
        for (int i = 0; i < 8; i++) {
            int g = tid * 8 + i;
            int code = g >> 4, u = g & 15;
            dsto[i] = (uint32_t)(code * 272 + u * 16);
            srco[i] = ebase + (uint64_t)(code * 512 + u * 16);
        }
    }
    // chunk j (0..15): nt = j>>1 (code tile), kh = j&1 (k-halves [kh*128,+128))
    auto issue_chunk = [&](int j) {
        const uint32_t dstb = sb + EB_OFF + (uint32_t)(j & 1) * EB_SZ;
        const uint64_t srcb = (uint64_t)((j >> 1) * 65536 + (j & 1) * 256);
        #pragma unroll
        for (int i = 0; i < 8; i++) {
            asm volatile("cp.async.cg.shared.global [%0], [%1], 16;"
                         :: "r"(dstb + dsto[i]), "l"(srco[i] + srcb) : "memory");
        }
        asm volatile("cp.async.commit_group;" ::: "memory");
    };

    issue_chunk(0);

    // ---------- phase 1: z load + fp16; stage enorm+0.5 ----------
    const float* zbase = z + (size_t)n_img * DIM * HW + hw0;
    {
        const int row = tid & 63;
        const int d0  = tid >> 6;          // 0..3
        __half* zh = (__half*)(smem + ZH_OFF);
        #pragma unroll 8
        for (int i = 0; i < 64; i++) {
            int d = 4 * i + d0;
            float v = zbase[((size_t)d << 10) + row];
            zh[row * 264 + d] = __float2half_rn(v);
        }
        float* se = (float*)(smem + EN_OFF);
        #pragma unroll
        for (int i = 0; i < 4; i++) se[tid + 256 * i] = g_enorm[tid + 256 * i] + 0.5f;
        __syncthreads();
    }

    int collo[8];
    #pragma unroll
    for (int q = 0; q < 4; q++)
        #pragma unroll
        for (int c = 0; c < 2; c++)
            collo[q * 2 + c] = wn * 32 + q * 8 + (lane & 3) * 2 + c;

    // ---------- phase 2: main loop (16 BIG chunks) ----------
    float acc[2][4][4];
    uint32_t top[2][2][2];
    #pragma unroll
    for (int a = 0; a < 2; a++)
        #pragma unroll
        for (int b = 0; b < 2; b++) { top[a][b][0] = 0xFFFFFFFFu; top[a][b][1] = 0xFFFFFFFFu; }

    const float* s_en = (const float*)(smem + EN_OFF);

    for (int j = 0; j < 16; j++) {
        const int nt = j >> 1, kh = j & 1;

        asm volatile("cp.async.wait_group 0;" ::: "memory");
        __syncthreads();                 // data visible to all; prior reads of the
                                         // other buffer are complete block-wide
        if (j + 1 < 16) issue_chunk(j + 1);   // overlaps compute of chunk j

        if (kh == 0) {
            #pragma unroll
            for (int mt = 0; mt < 2; mt++)
                #pragma unroll
                for (int q = 0; q < 4; q++)
                    #pragma unroll
                    for (int c = 0; c < 4; c++) acc[mt][q][c] = 0.f;
        }

        const uint32_t abase = sb + ZH_OFF;
        const uint32_t bbase = sb + EB_OFF + (uint32_t)(j & 1) * EB_SZ;
        const uint32_t arow  = (uint32_t)(wm * 32 + (lane & 15)) * 528u;
        const uint32_t alanec = (uint32_t)((lane >> 4) * 16);
        const uint32_t brow0 = (uint32_t)(wn * 32 + (lane & 15)) * 272u;
        #pragma unroll
        for (int ks = 0; ks < 8; ks++) {
            const uint32_t akb = (uint32_t)(kh * 256 + ks * 32) + alanec;
            uint32_t a0[4], a1[4];
            LDSM4(a0[0],a0[1],a0[2],a0[3], abase + arow + akb);
            LDSM4(a1[0],a1[1],a1[2],a1[3], abase + arow + 16u*528u + akb);
            const uint32_t bkb = (uint32_t)(ks * 32) + alanec;
            uint32_t br[2][4];
            LDSM4(br[0][0],br[0][1],br[0][2],br[0][3], bbase + brow0 + bkb);
            LDSM4(br[1][0],br[1][1],br[1][2],br[1][3], bbase + brow0 + 16u*272u + bkb);
            #pragma unroll
            for (int qq = 0; qq < 2; qq++) {
                MMA_F16(acc[0][2*qq],   a0[0],a0[1],a0[2],a0[3], br[qq][0], br[qq][2]);
                MMA_F16(acc[0][2*qq+1], a0[0],a0[1],a0[2],a0[3], br[qq][1], br[qq][3]);
                MMA_F16(acc[1][2*qq],   a1[0],a1[1],a1[2],a1[3], br[qq][0], br[qq][2]);
                MMA_F16(acc[1][2*qq+1], a1[0],a1[1],a1[2],a1[3], br[qq][1], br[qq][3]);
            }
        }

        if (kh == 1) {
            float enq[8]; uint32_t codes[8];
            #pragma unroll
            for (int e = 0; e < 8; e++) {
                enq[e]   = s_en[nt * 128 + collo[e]];
                codes[e] = (uint32_t)(nt * 128 + collo[e]);
            }
            #pragma unroll
            for (int mt = 0; mt < 2; mt++) {
                #pragma unroll
                for (int h = 0; h < 2; h++) {
                    #pragma unroll
                    for (int e = 0; e < 8; e++) {
                        const float v = fmaf(acc[mt][e >> 1][2*h + (e & 1)],
                                             -(1.0f/512.0f), enq[e]);
                        const uint32_t p = (__float_as_uint(v) & 0xFFFFFC00u) | codes[e];
                        const uint32_t t0 = top[mt][h][0];
                        const uint32_t cr = umax(t0, p);
                        top[mt][h][0] = umin(t0, p);
                        top[mt][h][1] = umin(top[mt][h][1], cr);
                    }
                }
            }
        }
    }

    // ---------- candidate merge ----------
    uint32_t L[2][2][4];
    #pragma unroll
    for (int mt = 0; mt < 2; mt++)
        #pragma unroll
        for (int h = 0; h < 2; h++) {
            L[mt][h][0] = top[mt][h][0]; L[mt][h][1] = top[mt][h][1];
            L[mt][h][2] = 0xFFFFFFFFu;   L[mt][h][3] = 0xFFFFFFFFu;
            #pragma unroll
            for (int off = 1; off <= 2; off <<= 1) {
                uint32_t o[4];
                #pragma unroll
                for (int k = 0; k < 4; k++)
                    o[k] = __shfl_xor_sync(0xffffffffu, L[mt][h][k], off);
                #pragma unroll
                for (int k = 0; k < 4; k++) ins4b(&L[mt][h][0], o[k]);
            }
        }

    uint32_t* cand = (uint32_t*)(smem + CAND_OFF);
    __syncthreads();
    if ((lane & 3) == 0) {
        #pragma unroll
        for (int mt = 0; mt < 2; mt++)
            #pragma unroll
            for (int h = 0; h < 2; h++) {
                int row = wm * 32 + mt * 16 + h * 8 + (lane >> 2);
                #pragma unroll
                for (int k = 0; k < 4; k++)
                    cand[(row * 4 + wn) * 4 + k] = L[mt][h][k];
            }
    }
    __syncthreads();
    if (wn == 0 && (lane & 3) == 0) {
        #pragma unroll
        for (int mt = 0; mt < 2; mt++)
            #pragma unroll
            for (int h = 0; h < 2; h++) {
                int row = wm * 32 + mt * 16 + h * 8 + (lane >> 2);
                #pragma unroll
                for (int w2 = 1; w2 < 4; w2++)
                    #pragma unroll
                    for (int k = 0; k < 4; k++)
                        ins4b(&L[mt][h][0], cand[(row * 4 + w2) * 4 + k]);
                // gap-gated commit: top-1 certain unless approx gap is tiny
                const int grow = m0 + row;
                g_idx[grow] = (int)(L[mt][h][0] & 1023u);
                const float v0 = __uint_as_float(L[mt][h][0] & 0xFFFFFC00u);
                const float v1 = __uint_as_float(L[mt][h][1] & 0xFFFFFC00u);
                if (v1 - v0 < GAP_THRESH) {
                    #pragma unroll
                    for (int k = 0; k < 4; k++)
                        g_cand[grow * 4 + k] = (int)(L[mt][h][k] & 1023u);
                    int pos = atomicAdd(&g_nwork, 1);
                    g_work[pos] = grow;
                }
            }
    }
}

// ==================== phase B: sparse exact fp32 rescore, wide interleaved ====================
__global__ void __launch_bounds__(32)
k_rescore(const float* __restrict__ z, const float* __restrict__ emb) {
    const int nw = g_nwork;
    #pragma unroll
    for (int it = 0; it < 2; it++) {
        const int i = blockIdx.x + 1024 * (threadIdx.x + 32 * it);
        if (i >= nw) break;
        const int row = g_work[i];
        const int n_img = row >> 10, hw = row & 1023;
        const float* zp = z + (size_t)n_img * DIM * HW + hw;

        int4 cn = *(const int4*)&g_cand[row * 4];
        const float4* e0 = (const float4*)(emb + ((size_t)cn.x << 8));
        const float4* e1 = (const float4*)(emb + ((size_t)cn.y << 8));
        const float4* e2 = (const float4*)(emb + ((size_t)cn.z << 8));
        const float4* e3 = (const float4*)(emb + ((size_t)cn.w << 8));

        float a0 = 0.f, a1 = 0.f, a2 = 0.f, a3 = 0.f, zn = 0.f;
        #pragma unroll 8
        for (int d4 = 0; d4 < 64; d4++) {
            float4 v0 = e0[d4], v1 = e1[d4], v2 = e2[d4], v3 = e3[d4];
            float zv;
            zv = zp[(size_t)(d4*4 + 0) << 10];
            zn = fmaf(zv, zv, zn);
            a0 = fmaf(zv, v0.x, a0); a1 = fmaf(zv, v1.x, a1);
            a2 = fmaf(zv, v2.x, a2); a3 = fmaf(zv, v3.x, a3);
            zv = zp[(size_t)(d4*4 + 1) << 10];
            zn = fmaf(zv, zv, zn);
            a0 = fmaf(zv, v0.y, a0); a1 = fmaf(zv, v1.y, a1);
            a2 = fmaf(zv, v2.y, a2); a3 = fmaf(zv, v3.y, a3);
            zv = zp[(size_t)(d4*4 + 2) << 10];
            zn = fmaf(zv, zv, zn);
            a0 = fmaf(zv, v0.z, a0); a1 = fmaf(zv, v1.z, a1);
            a2 = fmaf(zv, v2.z, a2); a3 = fmaf(zv, v3.z, a3);
            zv = zp[(size_t)(d4*4 + 3) << 10];
            zn = fmaf(zv, zv, zn);
            a0 = fmaf(zv, v0.w, a0); a1 = fmaf(zv, v1.w, a1);
            a2 = fmaf(zv, v2.w, a2); a3 = fmaf(zv, v3.w, a3);
        }

        float bd; int bi;
        {
            float t = zn - 2.0f * a0; bd = t + g_enorm[cn.x]; bi = cn.x;
        }
        {
            float t = zn - 2.0f * a1; float d = t + g_enorm[cn.y];
            if (d < bd || (d == bd && cn.y < bi)) { bd = d; bi = cn.y; }
        }
        {
            float t = zn - 2.0f * a2; float d = t + g_enorm[cn.z];
            if (d < bd || (d == bd && cn.z < bi)) { bd = d; bi = cn.z; }
        }
        {
            float t = zn - 2.0f * a3; float d = t + g_enorm[cn.w];
            if (d < bd || (d == bd && cn.w < bi)) { bd = d; bi = cn.w; }
        }

        g_idx[row] = bi;
    }
}

// ==================== output + loss ====================
__global__ void __launch_bounds__(256)
k_out(const float* __restrict__ z, const float* __restrict__ emb,
      float* __restrict__ out_zq, float* __restrict__ out_idx) {
    int t    = blockIdx.x * 256 + threadIdx.x;
    int hw   = t & 1023;
    int rest = t >> 10;
    int db   = (rest & 63) << 2;
    int n    = rest >> 6;

    int idx = g_idx[(n << 10) + hw];
    if (db == 0) out_idx[(n << 10) + hw] = (float)idx;
    float4 e = *(const float4*)&emb[(size_t)idx * DIM + db];

    size_t zb = (((size_t)n * DIM + db) << 10) + hw;
    float z0 = z[zb], z1 = z[zb + 1024], z2 = z[zb + 2048], z3 = z[zb + 3072];

    out_zq[zb]        = z0 + (e.x - z0);
    out_zq[zb + 1024] = z1 + (e.y - z1);
    out_zq[zb + 2048] = z2 + (e.z - z2);
    out_zq[zb + 3072] = z3 + (e.w - z3);

    float d0 = z0 - e.x, d1 = z1 - e.y, d2 = z2 - e.z, d3 = z3 - e.w;
    float sq = d0*d0 + d1*d1 + d2*d2 + d3*d3;

    #pragma unroll
    for (int off = 16; off; off >>= 1) sq += __shfl_xor_sync(0xffffffffu, sq, off);

    __shared__ float wsum[8];
    int wid = threadIdx.x >> 5, lid = threadIdx.x & 31;
    if (lid == 0) wsum[wid] = sq;
    __syncthreads();
    if (threadIdx.x == 0) {
        float s = 0.f;
        #pragma unroll
        for (int w = 0; w < 8; w++) s += wsum[w];
        atomicAdd(&g_loss, (double)s);
    }
}

__global__ void k_fin(float* __restrict__ out_loss) {
    float m = (float)(g_loss / (double)ZQ_ELEMS);
    out_loss[0] = 0.02f * m + m;
}

extern "C" void kernel_launch(void* const* d_in, const int* in_sizes, int n_in,
                              void* d_out, int out_size) {
    const float* z   = (const float*)d_in[0];
    const float* emb = (const float*)d_in[1];
    float* out      = (float*)d_out;
    float* out_zq   = out;
    float* out_idx  = out + ZQ_ELEMS;
    float* out_loss = out + ZQ_ELEMS + MTOT;

    cudaFuncSetAttribute(k_argmin_mma, cudaFuncAttributeMaxDynamicSharedMemorySize, SMEM_ARG);

    k_enorm     <<<KCODES, 32>>>(emb);
    k_esplit    <<<256, 256>>>(emb);
    k_argmin_mma<<<MTOT / 64, 256, SMEM_ARG>>>(z);
    k_rescore   <<<1024, 32>>>(z, emb);
    k_out       <<<ZQ_ELEMS / (256 * 4), 256>>>(z, emb, out_zq, out_idx);
    k_fin       <<<1, 1>>>(out_loss);
}

// round 15
// speedup vs baseline: 1.1579x; 1.1579x over previous
#include <cuda_runtime.h>
#include <cuda_fp16.h>
#include <cstdint>

#define NIMG 64
#define DIM  256
#define HW   1024
#define MTOT 65536
#define KCODES 1024
#define ZQ_ELEMS 16777216

#define GAP_THRESH 6e-4f

__device__ float  g_enorm[KCODES];
__device__ int    g_idx[MTOT];
__device__ double g_loss;
__device__ __half g_ehi[KCODES * DIM];   // fp16(1024*emb)

// ---------------- smem layout (bytes), M-tile = 64, 4 E buffers (round-8/12 config) ----------------
#define ZH_OFF 0                  // 64 rows x 264 halves (528B stride) = 33792
#define EB_OFF 33792              // 4 x (128 codes x 72 halves, 144B stride)
#define EB_SZ  18432              // ends at 107520
#define EN_OFF 107520             // 1024 f32 (enorm + 0.5) -> 111616
#define SMEM_ARG 111616
// aliased after main loop (E buffers dead):
#define CAND_OFF EB_OFF                 // 64 rows x 4 wn x 4 u32 = 4096
#define LW_OFF  (EB_OFF + 4096)         // 64 ints: local gated rows
#define LC_OFF  (EB_OFF + 4352)         // 1 int: local counter
#define CC_OFF  (EB_OFF + 4416)         // 64 x 4 ints: candidate codes

__device__ __forceinline__ uint32_t smem_u32(const void* p) {
    uint32_t a;
    asm("{ .reg .u64 t; cvta.to.shared.u64 t, %1; cvt.u32.u64 %0, t; }" : "=r"(a) : "l"(p));
    return a;
}
#define LDSM4(r0,r1,r2,r3,addr) \
    asm volatile("ldmatrix.sync.aligned.m8n8.x4.shared.b16 {%0,%1,%2,%3}, [%4];" \
                 : "=r"(r0), "=r"(r1), "=r"(r2), "=r"(r3) : "r"(addr))
#define MMA_F16(c, a0,a1,a2,a3, b0,b1) \
    asm volatile("mma.sync.aligned.m16n8k16.row.col.f32.f16.f16.f32 " \
                 "{%0,%1,%2,%3}, {%4,%5,%6,%7}, {%8,%9}, {%0,%1,%2,%3};" \
                 : "+f"((c)[0]), "+f"((c)[1]), "+f"((c)[2]), "+f"((c)[3]) \
                 : "r"(a0), "r"(a1), "r"(a2), "r"(a3), "r"(b0), "r"(b1))

// insert p into ascending 4-list (branchless IMNMX chain) — merges only
__device__ __forceinline__ void ins4b(uint32_t* t, uint32_t p) {
    uint32_t c;
    c = umax(t[0], p); t[0] = umin(t[0], p);
    p = c;
    c = umax(t[1], p); t[1] = umin(t[1], p);
    p = c;
    c = umax(t[2], p); t[2] = umin(t[2], p);
    t[3] = umin(t[3], c);
}

// ==================== small kernels ====================
// identical to round-1 (bit-matching enorm values, used by exact rescore)
__global__ void k_enorm(const float* __restrict__ emb) {
    int k = blockIdx.x, lid = threadIdx.x;
    if (k == 0 && lid == 0) g_loss = 0.0;
    const float* p = emb + (size_t)k * DIM + lid * 8;
    float4 a = *(const float4*)p;
    float4 b = *(const float4*)(p + 4);
    float s = a.x*a.x; s = fmaf(a.y,a.y,s); s = fmaf(a.z,a.z,s); s = fmaf(a.w,a.w,s);
    s = fmaf(b.x,b.x,s); s = fmaf(b.y,b.y,s); s = fmaf(b.z,b.z,s); s = fmaf(b.w,b.w,s);
    #pragma unroll
    for (int off = 16; off; off >>= 1) s += __shfl_xor_sync(0xffffffffu, s, off);
    if (lid == 0) g_enorm[k] = s;
}

__global__ void k_esplit(const float* __restrict__ emb) {
    int t = blockIdx.x * 256 + threadIdx.x;
    #pragma unroll
    for (int i = 0; i < 4; i++) {
        int id = t * 4 + i;
        g_ehi[id] = __float2half_rn(emb[id] * 1024.0f);
    }
}

// ==================== phase A: candidate search + gap gate + fused sparse rescore ====================
__global__ void __launch_bounds__(256, 2)
k_argmin_mma(const float* __restrict__ z, const float* __restrict__ emb,
             float* __restrict__ out_idx) {
    extern __shared__ char smem[];
    const uint32_t sb = smem_u32(smem);
    const int tid = threadIdx.x;
    const int lane = tid & 31;
    const int warp = tid >> 5;
    const int wm = warp & 1;        // rows wm*32..+31
    const int wn = warp >> 1;       // cols wn*32..+31 within 128-code tile

    const int m0 = blockIdx.x * 64;
    const int n_img = m0 >> 10;
    const int hw0 = m0 & (HW - 1);

    uint32_t dsto[4]; uint64_t srco[4];
    {
        const uint64_t ebase = (uint64_t)__cvta_generic_to_global(g_ehi);
        #pragma unroll
        for (int i = 0; i < 4; i++) {
            int g = tid * 4 + i;
            int code = g >> 3, u = g & 7;
            dsto[i] = (uint32_t)(code * 144 + u * 16);
            srco[i] = ebase + (uint64_t)(code * 512 + u * 16);
        }
    }
    auto issue_chunk = [&](int j) {
        const uint32_t dstb = sb + EB_OFF + (uint32_t)(j & 3) * EB_SZ;
        const uint64_t srcb = (uint64_t)((j >> 2) * 65536 + (j & 3) * 128);
        #pragma unroll
        for (int i = 0; i < 4; i++) {
            asm volatile("cp.async.cg.shared.global [%0], [%1], 16;"
                         :: "r"(dstb + dsto[i]), "l"(srco[i] + srcb) : "memory");
        }
        asm volatile("cp.async.commit_group;" ::: "memory");
    };

    issue_chunk(0); issue_chunk(1); issue_chunk(2);

    // ---------- phase 1: z load + fp16; stage enorm+0.5 ----------
    const float* zbase = z + (size_t)n_img * DIM * HW + hw0;
    {
        const int row = tid & 63;
        const int d0  = tid >> 6;          // 0..3
        __half* zh = (__half*)(smem + ZH_OFF);
        #pragma unroll 8
        for (int i = 0; i < 64; i++) {
            int d = 4 * i + d0;
            float v = zbase[((size_t)d << 10) + row];
            zh[row * 264 + d] = __float2half_rn(v);
        }
        float* se = (float*)(smem + EN_OFF);
        #pragma unroll
        for (int i = 0; i < 4; i++) se[tid + 256 * i] = g_enorm[tid + 256 * i] + 0.5f;
        __syncthreads();
    }

    int collo[8];
    #pragma unroll
    for (int q = 0; q < 4; q++)
        #pragma unroll
        for (int c = 0; c < 2; c++)
            collo[q * 2 + c] = wn * 32 + q * 8 + (lane & 3) * 2 + c;

    // ---------- phase 2: main loop (32 chunks, depth-3 ring — known-good) ----------
    float acc[2][4][4];
    uint32_t top[2][2][2];
    #pragma unroll
    for (int a = 0; a < 2; a++)
        #pragma unroll
        for (int b = 0; b < 2; b++) { top[a][b][0] = 0xFFFFFFFFu; top[a][b][1] = 0xFFFFFFFFu; }

    const float* s_en = (const float*)(smem + EN_OFF);

    for (int j = 0; j < 32; j++) {
        const int nt = j >> 2, kc = j & 3;

        if (j < 30)       asm volatile("cp.async.wait_group 2;" ::: "memory");
        else if (j == 30) asm volatile("cp.async.wait_group 1;" ::: "memory");
        else              asm volatile("cp.async.wait_group 0;" ::: "memory");
        __syncthreads();
        if (j + 3 < 32) issue_chunk(j + 3);

        if (kc == 0) {
            #pragma unroll
            for (int mt = 0; mt < 2; mt++)
                #pragma unroll
                for (int q = 0; q < 4; q++)
                    #pragma unroll
                    for (int c = 0; c < 4; c++) acc[mt][q][c] = 0.f;
        }

        const uint32_t abase = sb + ZH_OFF;
        const uint32_t bbase = sb + EB_OFF + (uint32_t)(j & 3) * EB_SZ;
        const uint32_t arow  = (uint32_t)(wm * 32 + (lane & 15)) * 528u;
        const uint32_t alanec = (uint32_t)((lane >> 4) * 16);
        const uint32_t brow0 = (uint32_t)(wn * 32 + (lane & 15)) * 144u;
        #pragma unroll
        for (int ks = 0; ks < 4; ks++) {
            const uint32_t akb = (uint32_t)(kc * 128 + ks * 32) + alanec;
            uint32_t a0[4], a1[4];
            LDSM4(a0[0],a0[1],a0[2],a0[3], abase + arow + akb);
            LDSM4(a1[0],a1[1],a1[2],a1[3], abase + arow + 16u*528u + akb);
            const uint32_t bkb = (uint32_t)(ks * 32) + alanec;
            uint32_t br[2][4];
            LDSM4(br[0][0],br[0][1],br[0][2],br[0][3], bbase + brow0 + bkb);
            LDSM4(br[1][0],br[1][1],br[1][2],br[1][3], bbase + brow0 + 16u*144u + bkb);
            #pragma unroll
            for (int qq = 0; qq < 2; qq++) {
                MMA_F16(acc[0][2*qq],   a0[0],a0[1],a0[2],a0[3], br[qq][0], br[qq][2]);
                MMA_F16(acc[0][2*qq+1], a0[0],a0[1],a0[2],a0[3], br[qq][1], br[qq][3]);
                MMA_F16(acc[1][2*qq],   a1[0],a1[1],a1[2],a1[3], br[qq][0], br[qq][2]);
                MMA_F16(acc[1][2*qq+1], a1[0],a1[1],a1[2],a1[3], br[qq][1], br[qq][3]);
            }
        }

        if (kc == 3) {
            float enq[8]; uint32_t codes[8];
            #pragma unroll
            for (int e = 0; e < 8; e++) {
                enq[e]   = s_en[nt * 128 + collo[e]];
                codes[e] = (uint32_t)(nt * 128 + collo[e]);
            }
            #pragma unroll
            for (int mt = 0; mt < 2; mt++) {
                #pragma unroll
                for (int h = 0; h < 2; h++) {
                    #pragma unroll
                    for (int e = 0; e < 8; e++) {
                        const float v = fmaf(acc[mt][e >> 1][2*h + (e & 1)],
                                             -(1.0f/512.0f), enq[e]);
                        const uint32_t p = (__float_as_uint(v) & 0xFFFFFC00u) | codes[e];
                        const uint32_t t0 = top[mt][h][0];
                        const uint32_t cr = umax(t0, p);
                        top[mt][h][0] = umin(t0, p);
                        top[mt][h][1] = umin(top[mt][h][1], cr);
                    }
                }
            }
        }
    }

    // ---------- candidate merge ----------
    uint32_t L[2][2][4];
    #pragma unroll
    for (int mt = 0; mt < 2; mt++)
        #pragma unroll
        for (int h = 0; h < 2; h++) {
            L[mt][h][0] = top[mt][h][0]; L[mt][h][1] = top[mt][h][1];
            L[mt][h][2] = 0xFFFFFFFFu;   L[mt][h][3] = 0xFFFFFFFFu;
            #pragma unroll
            for (int off = 1; off <= 2; off <<= 1) {
                uint32_t o[4];
                #pragma unroll
                for (int k = 0; k < 4; k++)
                    o[k] = __shfl_xor_sync(0xffffffffu, L[mt][h][k], off);
                #pragma unroll
                for (int k = 0; k < 4; k++) ins4b(&L[mt][h][0], o[k]);
            }
        }

    uint32_t* cand = (uint32_t*)(smem + CAND_OFF);
    int* lw  = (int*)(smem + LW_OFF);
    int* lc  = (int*)(smem + LC_OFF);
    int* cc  = (int*)(smem + CC_OFF);
    __syncthreads();   // all LDSM reads of EB done -> safe to alias
    if (tid == 0) *lc = 0;
    if ((lane & 3) == 0) {
        #pragma unroll
        for (int mt = 0; mt < 2; mt++)
            #pragma unroll
            for (int h = 0; h < 2; h++) {
                int row = wm * 32 + mt * 16 + h * 8 + (lane >> 2);
                #pragma unroll
                for (int k = 0; k < 4; k++)
                    cand[(row * 4 + wn) * 4 + k] = L[mt][h][k];
            }
    }
    __syncthreads();
    if (wn == 0 && (lane & 3) == 0) {
        #pragma unroll
        for (int mt = 0; mt < 2; mt++)
            #pragma unroll
            for (int h = 0; h < 2; h++) {
                int row = wm * 32 + mt * 16 + h * 8 + (lane >> 2);
                #pragma unroll
                for (int w2 = 1; w2 < 4; w2++)
                    #pragma unroll
                    for (int k = 0; k < 4; k++)
                        ins4b(&L[mt][h][0], cand[(row * 4 + w2) * 4 + k]);
                // gap-gated commit; uncertain rows go on the block-local worklist
                g_idx[m0 + row] = (int)(L[mt][h][0] & 1023u);
                const float v0 = __uint_as_float(L[mt][h][0] & 0xFFFFFC00u);
                const float v1 = __uint_as_float(L[mt][h][1] & 0xFFFFFC00u);
                if (v1 - v0 < GAP_THRESH) {
                    int pos = atomicAdd(lc, 1);
                    lw[pos] = row;
                    #pragma unroll
                    for (int k = 0; k < 4; k++)
                        cc[pos * 4 + k] = (int)(L[mt][h][k] & 1023u);
                }
            }
    }
    __syncthreads();

    // ---------- fused sparse exact rescore (z slice is L2-hot) ----------
    const int nloc = *lc;
    if (nloc > 0) {
        const int nact = (nloc + 7) & ~7;      // pad to whole warps (4 thr/row)
        if (tid < 4 * nact) {
            const int li = tid >> 2, c = tid & 3;
            const int lic = li < nloc ? li : nloc - 1;   // clamp padding threads
            const int row = lw[lic];
            const int ci  = cc[lic * 4 + c];
            const float* zp = zbase + row;
            const float4* ev = (const float4*)(emb + ((size_t)ci << 8));

            float a = 0.f, zn = 0.f;
            #pragma unroll 8
            for (int d4 = 0; d4 < 64; d4++) {
                float4 v = ev[d4];
                float zv;
                zv = zp[(size_t)(d4*4 + 0) << 10];
                zn = fmaf(zv, zv, zn); a = fmaf(zv, v.x, a);
                zv = zp[(size_t)(d4*4 + 1) << 10];
                zn = fmaf(zv, zv, zn); a = fmaf(zv, v.y, a);
                zv = zp[(size_t)(d4*4 + 2) << 10];
                zn = fmaf(zv, zv, zn); a = fmaf(zv, v.z, a);
                zv = zp[(size_t)(d4*4 + 3) << 10];
                zn = fmaf(zv, zv, zn); a = fmaf(zv, v.w, a);
            }
            float t = zn - 2.0f * a;
            float d = t + g_enorm[ci];
            int  bi = ci;
            // 4-lane lexicographic (d, idx) min — total order => tree min == fold
            #pragma unroll
            for (int off = 1; off <= 2; off <<= 1) {
                float od = __shfl_xor_sync(0xffffffffu, d, off);
                int   oi = __shfl_xor_sync(0xffffffffu, bi, off);
                if (od < d || (od == d && oi < bi)) { d = od; bi = oi; }
            }
            if (c == 0 && li < nloc) g_idx[m0 + row] = bi;
        }
    }
}

// ==================== output + loss ====================
__global__ void __launch_bounds__(256)
k_out(const float* __restrict__ z, const float* __restrict__ emb,
      float* __restrict__ out_zq, float* __restrict__ out_idx) {
    int t    = blockIdx.x * 256 + threadIdx.x;
    int hw   = t & 1023;
    int rest = t >> 10;
    int db   = (rest & 63) << 2;
    int n    = rest >> 6;

    int idx = g_idx[(n << 10) + hw];
    if (db == 0) out_idx[(n << 10) + hw] = (float)idx;
    float4 e = *(const float4*)&emb[(size_t)idx * DIM + db];

    size_t zb = (((size_t)n * DIM + db) << 10) + hw;
    float z0 = z[zb], z1 = z[zb + 1024], z2 = z[zb + 2048], z3 = z[zb + 3072];

    out_zq[zb]        = z0 + (e.x - z0);
    out_zq[zb + 1024] = z1 + (e.y - z1);
    out_zq[zb + 2048] = z2 + (e.z - z2);
    out_zq[zb + 3072] = z3 + (e.w - z3);

    float d0 = z0 - e.x, d1 = z1 - e.y, d2 = z2 - e.z, d3 = z3 - e.w;
    float sq = d0*d0 + d1*d1 + d2*d2 + d3*d3;

    #pragma unroll
    for (int off = 16; off; off >>= 1) sq += __shfl_xor_sync(0xffffffffu, sq, off);

    __shared__ float wsum[8];
    int wid = threadIdx.x >> 5, lid = threadIdx.x & 31;
    if (lid == 0) wsum[wid] = sq;
    __syncthreads();
    if (threadIdx.x == 0) {
        float s = 0.f;
        #pragma unroll
        for (int w = 0; w < 8; w++) s += wsum[w];
        atomicAdd(&g_loss, (double)s);
    }
}

__global__ void k_fin(float* __restrict__ out_loss) {
    float m = (float)(g_loss / (double)ZQ_ELEMS);
    out_loss[0] = 0.02f * m + m;
}

extern "C" void kernel_launch(void* const* d_in, const int* in_sizes, int n_in,
                              void* d_out, int out_size) {
    const float* z   = (const float*)d_in[0];
    const float* emb = (const float*)d_in[1];
    float* out      = (float*)d_out;
    float* out_zq   = out;
    float* out_idx  = out + ZQ_ELEMS;
    float* out_loss = out + ZQ_ELEMS + MTOT;

    cudaFuncSetAttribute(k_argmin_mma, cudaFuncAttributeMaxDynamicSharedMemorySize, SMEM_ARG);

    k_enorm     <<<KCODES, 32>>>(emb);
    k_esplit    <<<256, 256>>>(emb);
    k_argmin_mma<<<MTOT / 64, 256, SMEM_ARG>>>(z, emb, out_idx);
    k_out       <<<ZQ_ELEMS / (256 * 4), 256>>>(z, emb, out_zq, out_idx);
    k_fin       <<<1, 1>>>(out_loss);
}

// round 16
// speedup vs baseline: 1.2100x; 1.0450x over previous
#include <cuda_runtime.h>
#include <cuda_fp16.h>
#include <cstdint>

#define NIMG 64
#define DIM  256
#define HW   1024
#define MTOT 65536
#define KCODES 1024
#define ZQ_ELEMS 16777216

#define GAP_THRESH 6e-4f

__device__ float  g_enorm[KCODES];
__device__ int    g_idx[MTOT];
__device__ double g_loss;
__device__ __half g_ehi[KCODES * DIM];   // fp16(1024*emb)

// ---------------- smem layout (bytes), M-tile = 64, 4 E buffers (round-8/12 config) ----------------
#define ZH_OFF 0                  // 64 rows x 264 halves (528B stride) = 33792
#define EB_OFF 33792              // 4 x (128 codes x 72 halves, 144B stride)
#define EB_SZ  18432              // ends at 107520
#define EN_OFF 107520             // 1024 f32 (enorm + 0.5) -> 111616
#define SMEM_ARG 111616
// aliased after main loop (E buffers dead):
#define CAND_OFF EB_OFF                 // 64 rows x 4 wn x 4 u32 = 4096
#define LW_OFF  (EB_OFF + 4096)         // 64 ints: local gated rows
#define LC_OFF  (EB_OFF + 4352)         // 1 int: local counter
#define CC_OFF  (EB_OFF + 4416)         // 64 x 4 ints: candidate codes

__device__ __forceinline__ uint32_t smem_u32(const void* p) {
    uint32_t a;
    asm("{ .reg .u64 t; cvta.to.shared.u64 t, %1; cvt.u32.u64 %0, t; }" : "=r"(a) : "l"(p));
    return a;
}
#define LDSM4(r0,r1,r2,r3,addr) \
    asm volatile("ldmatrix.sync.aligned.m8n8.x4.shared.b16 {%0,%1,%2,%3}, [%4];" \
                 : "=r"(r0), "=r"(r1), "=r"(r2), "=r"(r3) : "r"(addr))
#define MMA_F16(c, a0,a1,a2,a3, b0,b1) \
    asm volatile("mma.sync.aligned.m16n8k16.row.col.f32.f16.f16.f32 " \
                 "{%0,%1,%2,%3}, {%4,%5,%6,%7}, {%8,%9}, {%0,%1,%2,%3};" \
                 : "+f"((c)[0]), "+f"((c)[1]), "+f"((c)[2]), "+f"((c)[3]) \
                 : "r"(a0), "r"(a1), "r"(a2), "r"(a3), "r"(b0), "r"(b1))

// insert p into ascending 4-list (branchless IMNMX chain) — merges only
__device__ __forceinline__ void ins4b(uint32_t* t, uint32_t p) {
    uint32_t c;
    c = umax(t[0], p); t[0] = umin(t[0], p);
    p = c;
    c = umax(t[1], p); t[1] = umin(t[1], p);
    p = c;
    c = umax(t[2], p); t[2] = umin(t[2], p);
    t[3] = umin(t[3], c);
}

// ==================== fused prep: enorm (round-1 bit-exact) + fp16 split ====================
__global__ void k_prep(const float* __restrict__ emb) {
    int k = blockIdx.x, lid = threadIdx.x;
    if (k == 0 && lid == 0) g_loss = 0.0;
    const float* p = emb + (size_t)k * DIM + lid * 8;
    float4 a = *(const float4*)p;
    float4 b = *(const float4*)(p + 4);
    // fp16 split of 1024*emb (exact power-of-2 scale)
    __half2* eh = (__half2*)(g_ehi + (size_t)k * DIM + lid * 8);
    eh[0] = __floats2half2_rn(a.x * 1024.0f, a.y * 1024.0f);
    eh[1] = __floats2half2_rn(a.z * 1024.0f, a.w * 1024.0f);
    eh[2] = __floats2half2_rn(b.x * 1024.0f, b.y * 1024.0f);
    eh[3] = __floats2half2_rn(b.z * 1024.0f, b.w * 1024.0f);
    // enorm, identical fp32 chain to round-1 (rescore bit-match depends on it)
    float s = a.x*a.x; s = fmaf(a.y,a.y,s); s = fmaf(a.z,a.z,s); s = fmaf(a.w,a.w,s);
    s = fmaf(b.x,b.x,s); s = fmaf(b.y,b.y,s); s = fmaf(b.z,b.z,s); s = fmaf(b.w,b.w,s);
    #pragma unroll
    for (int off = 16; off; off >>= 1) s += __shfl_xor_sync(0xffffffffu, s, off);
    if (lid == 0) g_enorm[k] = s;
}

// ==================== phase A: candidate search + gap gate + fused sparse rescore ====================
__global__ void __launch_bounds__(256, 2)
k_argmin_mma(const float* __restrict__ z, const float* __restrict__ emb,
             float* __restrict__ out_idx) {
    extern __shared__ char smem[];
    const uint32_t sb = smem_u32(smem);
    const int tid = threadIdx.x;
    const int lane = tid & 31;
    const int warp = tid >> 5;
    const int wm = warp & 1;        // rows wm*32..+31
    const int wn = warp >> 1;       // cols wn*32..+31 within 128-code tile

    const int m0 = blockIdx.x * 64;
    const int n_img = m0 >> 10;
    const int hw0 = m0 & (HW - 1);

    uint32_t dsto[4]; uint64_t srco[4];
    {
        const uint64_t ebase = (uint64_t)__cvta_generic_to_global(g_ehi);
        #pragma unroll
        for (int i = 0; i < 4; i++) {
            int g = tid * 4 + i;
            int code = g >> 3, u = g & 7;
            dsto[i] = (uint32_t)(code * 144 + u * 16);
            srco[i] = ebase + (uint64_t)(code * 512 + u * 16);
        }
    }
    auto issue_chunk = [&](int j) {
        const uint32_t dstb = sb + EB_OFF + (uint32_t)(j & 3) * EB_SZ;
        const uint64_t srcb = (uint64_t)((j >> 2) * 65536 + (j & 3) * 128);
        #pragma unroll
        for (int i = 0; i < 4; i++) {
            asm volatile("cp.async.cg.shared.global [%0], [%1], 16;"
                         :: "r"(dstb + dsto[i]), "l"(srco[i] + srcb) : "memory");
        }
        asm volatile("cp.async.commit_group;" ::: "memory");
    };

    issue_chunk(0); issue_chunk(1); issue_chunk(2);

    // ---------- phase 1: z load + fp16; stage enorm+0.5 ----------
    const float* zbase = z + (size_t)n_img * DIM * HW + hw0;
    {
        const int row = tid & 63;
        const int d0  = tid >> 6;          // 0..3
        __half* zh = (__half*)(smem + ZH_OFF);
        #pragma unroll 8
        for (int i = 0; i < 64; i++) {
            int d = 4 * i + d0;
            float v = zbase[((size_t)d << 10) + row];
            zh[row * 264 + d] = __float2half_rn(v);
        }
        float* se = (float*)(smem + EN_OFF);
        #pragma unroll
        for (int i = 0; i < 4; i++) se[tid + 256 * i] = g_enorm[tid + 256 * i] + 0.5f;
        __syncthreads();
    }

    int collo[8];
    #pragma unroll
    for (int q = 0; q < 4; q++)
        #pragma unroll
        for (int c = 0; c < 2; c++)
            collo[q * 2 + c] = wn * 32 + q * 8 + (lane & 3) * 2 + c;

    // ---------- phase 2: main loop (32 chunks, depth-3 ring — known-good) ----------
    float acc[2][4][4];
    uint32_t top[2][2][2];
    #pragma unroll
    for (int a = 0; a < 2; a++)
        #pragma unroll
        for (int b = 0; b < 2; b++) { top[a][b][0] = 0xFFFFFFFFu; top[a][b][1] = 0xFFFFFFFFu; }

    const float* s_en = (const float*)(smem + EN_OFF);

    for (int j = 0; j < 32; j++) {
        const int nt = j >> 2, kc = j & 3;

        if (j < 30)       asm volatile("cp.async.wait_group 2;" ::: "memory");
        else if (j == 30) asm volatile("cp.async.wait_group 1;" ::: "memory");
        else              asm volatile("cp.async.wait_group 0;" ::: "memory");
        __syncthreads();
        if (j + 3 < 32) issue_chunk(j + 3);

        if (kc == 0) {
            #pragma unroll
            for (int mt = 0; mt < 2; mt++)
                #pragma unroll
                for (int q = 0; q < 4; q++)
                    #pragma unroll
                    for (int c = 0; c < 4; c++) acc[mt][q][c] = 0.f;
        }

        const uint32_t abase = sb + ZH_OFF;
        const uint32_t bbase = sb + EB_OFF + (uint32_t)(j & 3) * EB_SZ;
        const uint32_t arow  = (uint32_t)(wm * 32 + (lane & 15)) * 528u;
        const uint32_t alanec = (uint32_t)((lane >> 4) * 16);
        const uint32_t brow0 = (uint32_t)(wn * 32 + (lane & 15)) * 144u;
        #pragma unroll
        for (int ks = 0; ks < 4; ks++) {
            const uint32_t akb = (uint32_t)(kc * 128 + ks * 32) + alanec;
            uint32_t a0[4], a1[4];
            LDSM4(a0[0],a0[1],a0[2],a0[3], abase + arow + akb);
            LDSM4(a1[0],a1[1],a1[2],a1[3], abase + arow + 16u*528u + akb);
            const uint32_t bkb = (uint32_t)(ks * 32) + alanec;
            uint32_t br[2][4];
            LDSM4(br[0][0],br[0][1],br[0][2],br[0][3], bbase + brow0 + bkb);
            LDSM4(br[1][0],br[1][1],br[1][2],br[1][3], bbase + brow0 + 16u*144u + bkb);
            #pragma unroll
            for (int qq = 0; qq < 2; qq++) {
                MMA_F16(acc[0][2*qq],   a0[0],a0[1],a0[2],a0[3], br[qq][0], br[qq][2]);
                MMA_F16(acc[0][2*qq+1], a0[0],a0[1],a0[2],a0[3], br[qq][1], br[qq][3]);
                MMA_F16(acc[1][2*qq],   a1[0],a1[1],a1[2],a1[3], br[qq][0], br[qq][2]);
                MMA_F16(acc[1][2*qq+1], a1[0],a1[1],a1[2],a1[3], br[qq][1], br[qq][3]);
            }
        }

        if (kc == 3) {
            float enq[8]; uint32_t codes[8];
            #pragma unroll
            for (int e = 0; e < 8; e++) {
                enq[e]   = s_en[nt * 128 + collo[e]];
                codes[e] = (uint32_t)(nt * 128 + collo[e]);
            }
            #pragma unroll
            for (int mt = 0; mt < 2; mt++) {
                #pragma unroll
                for (int h = 0; h < 2; h++) {
                    #pragma unroll
                    for (int e = 0; e < 8; e++) {
                        const float v = fmaf(acc[mt][e >> 1][2*h + (e & 1)],
                                             -(1.0f/512.0f), enq[e]);
                        const uint32_t p = (__float_as_uint(v) & 0xFFFFFC00u) | codes[e];
                        const uint32_t t0 = top[mt][h][0];
                        const uint32_t cr = umax(t0, p);
                        top[mt][h][0] = umin(t0, p);
                        top[mt][h][1] = umin(top[mt][h][1], cr);
                    }
                }
            }
        }
    }

    // ---------- candidate merge ----------
    uint32_t L[2][2][4];
    #pragma unroll
    for (int mt = 0; mt < 2; mt++)
        #pragma unroll
        for (int h = 0; h < 2; h++) {
            L[mt][h][0] = top[mt][h][0]; L[mt][h][1] = top[mt][h][1];
            L[mt][h][2] = 0xFFFFFFFFu;   L[mt][h][3] = 0xFFFFFFFFu;
            #pragma unroll
            for (int off = 1; off <= 2; off <<= 1) {
                uint32_t o[4];
                #pragma unroll
                for (int k = 0; k < 4; k++)
                    o[k] = __shfl_xor_sync(0xffffffffu, L[mt][h][k], off);
                #pragma unroll
                for (int k = 0; k < 4; k++) ins4b(&L[mt][h][0], o[k]);
            }
        }

    uint32_t* cand = (uint32_t*)(smem + CAND_OFF);
    int* lw  = (int*)(smem + LW_OFF);
    int* lc  = (int*)(smem + LC_OFF);
    int* cc  = (int*)(smem + CC_OFF);
    __syncthreads();   // all LDSM reads of EB done -> safe to alias
    if (tid == 0) *lc = 0;
    if ((lane & 3) == 0) {
        #pragma unroll
        for (int mt = 0; mt < 2; mt++)
            #pragma unroll
            for (int h = 0; h < 2; h++) {
                int row = wm * 32 + mt * 16 + h * 8 + (lane >> 2);
                #pragma unroll
                for (int k = 0; k < 4; k++)
                    cand[(row * 4 + wn) * 4 + k] = L[mt][h][k];
            }
    }
    __syncthreads();
    if (wn == 0 && (lane & 3) == 0) {
        #pragma unroll
        for (int mt = 0; mt < 2; mt++)
            #pragma unroll
            for (int h = 0; h < 2; h++) {
                int row = wm * 32 + mt * 16 + h * 8 + (lane >> 2);
                #pragma unroll
                for (int w2 = 1; w2 < 4; w2++)
                    #pragma unroll
                    for (int k = 0; k < 4; k++)
                        ins4b(&L[mt][h][0], cand[(row * 4 + w2) * 4 + k]);
                // gap-gated commit; uncertain rows go on the block-local worklist
                g_idx[m0 + row] = (int)(L[mt][h][0] & 1023u);
                const float v0 = __uint_as_float(L[mt][h][0] & 0xFFFFFC00u);
                const float v1 = __uint_as_float(L[mt][h][1] & 0xFFFFFC00u);
                if (v1 - v0 < GAP_THRESH) {
                    int pos = atomicAdd(lc, 1);
                    lw[pos] = row;
                    #pragma unroll
                    for (int k = 0; k < 4; k++)
                        cc[pos * 4 + k] = (int)(L[mt][h][k] & 1023u);
                }
            }
    }
    __syncthreads();

    // ---------- fused sparse exact rescore (z slice is L2-hot) ----------
    const int nloc = *lc;
    if (nloc > 0) {
        const int nact = (nloc + 7) & ~7;      // pad to whole warps (4 thr/row)
        if (tid < 4 * nact) {
            const int li = tid >> 2, c = tid & 3;
            const int lic = li < nloc ? li : nloc - 1;   // clamp padding threads
            const int row = lw[lic];
            const int ci  = cc[lic * 4 + c];
            const float* zp = zbase + row;
            const float4* ev = (const float4*)(emb + ((size_t)ci << 8));

            float a = 0.f, zn = 0.f;
            #pragma unroll 8
            for (int d4 = 0; d4 < 64; d4++) {
                float4 v = ev[d4];
                float zv;
                zv = zp[(size_t)(d4*4 + 0) << 10];
                zn = fmaf(zv, zv, zn); a = fmaf(zv, v.x, a);
                zv = zp[(size_t)(d4*4 + 1) << 10];
                zn = fmaf(zv, zv, zn); a = fmaf(zv, v.y, a);
                zv = zp[(size_t)(d4*4 + 2) << 10];
                zn = fmaf(zv, zv, zn); a = fmaf(zv, v.z, a);
                zv = zp[(size_t)(d4*4 + 3) << 10];
                zn = fmaf(zv, zv, zn); a = fmaf(zv, v.w, a);
            }
            float t = zn - 2.0f * a;
            float d = t + g_enorm[ci];
            int  bi = ci;
            #pragma unroll
            for (int off = 1; off <= 2; off <<= 1) {
                float od = __shfl_xor_sync(0xffffffffu, d, off);
                int   oi = __shfl_xor_sync(0xffffffffu, bi, off);
                if (od < d || (od == d && oi < bi)) { d = od; bi = oi; }
            }
            if (c == 0 && li < nloc) g_idx[m0 + row] = bi;
        }
    }
}

// ==================== output + loss: 8 d per thread ====================
__global__ void __launch_bounds__(256)
k_out(const float* __restrict__ z, const float* __restrict__ emb,
      float* __restrict__ out_zq, float* __restrict__ out_idx) {
    int t    = blockIdx.x * 256 + threadIdx.x;   // 2,097,152 threads
    int hw   = t & 1023;
    int rest = t >> 10;
    int db   = (rest & 31) << 3;                 // d block of 8
    int n    = rest >> 5;

    int idx = g_idx[(n << 10) + hw];
    if (db == 0) out_idx[(n << 10) + hw] = (float)idx;
    const float4* ep = (const float4*)&emb[(size_t)idx * DIM + db];
    float4 e0 = ep[0], e1 = ep[1];

    size_t zb = (((size_t)n * DIM + db) << 10) + hw;
    float sq = 0.f;
    float ev[8] = {e0.x, e0.y, e0.z, e0.w, e1.x, e1.y, e1.z, e1.w};
    #pragma unroll
    for (int i = 0; i < 8; i++) {
        float zv = z[zb + ((size_t)i << 10)];
        out_zq[zb + ((size_t)i << 10)] = zv + (ev[i] - zv);
        float df = zv - ev[i];
        sq = fmaf(df, df, sq);
    }

    #pragma unroll
    for (int off = 16; off; off >>= 1) sq += __shfl_xor_sync(0xffffffffu, sq, off);

    __shared__ float wsum[8];
    int wid = threadIdx.x >> 5, lid = threadIdx.x & 31;
    if (lid == 0) wsum[wid] = sq;
    __syncthreads();
    if (threadIdx.x == 0) {
        float s = 0.f;
        #pragma unroll
        for (int w = 0; w < 8; w++) s += wsum[w];
        atomicAdd(&g_loss, (double)s);
    }
}

__global__ void k_fin(float* __restrict__ out_loss) {
    float m = (float)(g_loss / (double)ZQ_ELEMS);
    out_loss[0] = 0.02f * m + m;
}

extern "C" void kernel_launch(void* const* d_in, const int* in_sizes, int n_in,
                              void* d_out, int out_size) {
    const float* z   = (const float*)d_in[0];
    const float* emb = (const float*)d_in[1];
    float* out      = (float*)d_out;
    float* out_zq   = out;
    float* out_idx  = out + ZQ_ELEMS;
    float* out_loss = out + ZQ_ELEMS + MTOT;

    cudaFuncSetAttribute(k_argmin_mma, cudaFuncAttributeMaxDynamicSharedMemorySize, SMEM_ARG);

    k_prep      <<<KCODES, 32>>>(emb);
    k_argmin_mma<<<MTOT / 64, 256, SMEM_ARG>>>(z, emb, out_idx);
    k_out       <<<ZQ_ELEMS / (256 * 8), 256>>>(z, emb, out_zq, out_idx);
    k_fin       <<<1, 1>>>(out_loss);
}